// round 1
// baseline (speedup 1.0000x reference)
#include <cuda_runtime.h>
#include <cstdint>

// Problem constants (fixed by the reference)
#define M_TOK 256
#define K_DIM 1024
#define N_DIM 2048
#define E_NUM 64
#define TOPK  8
#define L_ROWS (M_TOK * TOPK)     // 2048 routed rows
#define CAP    (L_ROWS / E_NUM)   // 32 rows per expert (balanced routing, exact)

// GEMM tiling
#define BM 32
#define BN 128
#define BK 32
#define STRIDE 36                 // smem row stride (words): conflict-free for STS.128 + frag LDS
#define THREADS 128               // 4 warps; each warp owns 32m x 32n

// Scratch (no allocations allowed)
__device__ int   g_slots[E_NUM * CAP];     // flattened (m*TOPK+t) index per expert slot
__device__ float g_Atf[M_TOK * K_DIM];     // A pre-rounded to tf32

// ---------------------------------------------------------------------------
// Routing: bucket the 2048 (token, topk) slots by expert. Balanced routing
// guarantees exactly CAP per expert. Fill order is non-deterministic but the
// final output is order-invariant (each slot writes its own out row).
// ---------------------------------------------------------------------------
__global__ void route_kernel(const int* __restrict__ ids) {
    __shared__ int cnt[E_NUM];
    int t = threadIdx.x;
    if (t < E_NUM) cnt[t] = 0;
    __syncthreads();
    for (int l = t; l < L_ROWS; l += blockDim.x) {
        int e = ids[l];
        int p = atomicAdd(&cnt[e], 1);
        g_slots[e * CAP + p] = l;
    }
}

__device__ __forceinline__ float to_tf32(float x) {
    uint32_t r;
    asm("cvt.rna.tf32.f32 %0, %1;" : "=r"(r) : "f"(x));
    return __uint_as_float(r);
}

__global__ void cvtA_kernel(const float* __restrict__ A) {
    int i = blockIdx.x * blockDim.x + threadIdx.x;
    if (i < M_TOK * K_DIM) g_Atf[i] = to_tf32(A[i]);
}

__device__ __forceinline__ void mma_tf32(float c[4], const uint32_t a[4], const uint32_t b[2]) {
    asm volatile(
        "mma.sync.aligned.m16n8k8.row.col.f32.tf32.tf32.f32 "
        "{%0,%1,%2,%3}, {%4,%5,%6,%7}, {%8,%9}, {%0,%1,%2,%3};"
        : "+f"(c[0]), "+f"(c[1]), "+f"(c[2]), "+f"(c[3])
        : "r"(a[0]), "r"(a[1]), "r"(a[2]), "r"(a[3]), "r"(b[0]), "r"(b[1]));
}

// ---------------------------------------------------------------------------
// Grouped GEMM: block (nx, e) computes rows of expert e (32 gathered tokens)
// against B[e][n0:n0+128][:].  D = A_gather @ B[e]^T, epilogue fuses bias,
// routing weight, and scatter to out[l].
// ---------------------------------------------------------------------------
__global__ __launch_bounds__(THREADS) void moe_gemm_kernel(
    const float* __restrict__ B,      // [E, N, K]
    const float* __restrict__ bias,   // [E, N]
    const float* __restrict__ tw,     // [M, TOPK] flat
    float* __restrict__ out)          // [L, N]
{
    __shared__ float As[BM * STRIDE];
    __shared__ float Bs[BN * STRIDE];
    __shared__ int   sSlot[CAP];
    __shared__ float sW[CAP];

    const int e    = blockIdx.y;
    const int n0   = blockIdx.x * BN;
    const int t    = threadIdx.x;
    const int warp = t >> 5;
    const int lane = t & 31;

    if (t < CAP) {
        int l = g_slots[e * CAP + t];
        sSlot[t] = l;
        sW[t]    = tw[l];
    }
    __syncthreads();

    const float* Bbase = B + ((size_t)e * N_DIM + n0) * K_DIM;

    float acc[2][4][4];
#pragma unroll
    for (int i = 0; i < 2; i++)
#pragma unroll
        for (int j = 0; j < 4; j++)
#pragma unroll
            for (int k = 0; k < 4; k++) acc[i][j][k] = 0.f;

    // staging thread mapping
    const int ma  = t & 31;     // A: row within tile
    const int kfa = t >> 5;     // A: float4 index (and +4)
    const int nb  = t >> 3;     // B: base n row (n = nb + j*16)
    const int kfb = t & 7;      // B: float4 index along k
    const float* arow = g_Atf + (size_t)(sSlot[ma] >> 3) * K_DIM;  // token row = l / TOPK

    float4 ra0, ra1, rb[8];

    // prologue: prefetch tile k0 = 0 into registers
    ra0 = *(const float4*)(arow + kfa * 4);
    ra1 = *(const float4*)(arow + (kfa + 4) * 4);
#pragma unroll
    for (int j = 0; j < 8; j++)
        rb[j] = *(const float4*)(Bbase + (size_t)(nb + j * 16) * K_DIM + kfb * 4);

    const uint32_t* Asu = (const uint32_t*)As;
    const uint32_t* Bsu = (const uint32_t*)Bs;

    for (int k0 = 0; k0 < K_DIM; k0 += BK) {
        // commit prefetched registers to smem (B rounded to tf32 here)
        *(float4*)(As + ma * STRIDE + kfa * 4)       = ra0;
        *(float4*)(As + ma * STRIDE + (kfa + 4) * 4) = ra1;
#pragma unroll
        for (int j = 0; j < 8; j++) {
            float4 v = rb[j];
            v.x = to_tf32(v.x); v.y = to_tf32(v.y);
            v.z = to_tf32(v.z); v.w = to_tf32(v.w);
            *(float4*)(Bs + (nb + j * 16) * STRIDE + kfb * 4) = v;
        }
        __syncthreads();

        // prefetch next tile while computing this one
        if (k0 + BK < K_DIM) {
            const int kn = k0 + BK;
            ra0 = *(const float4*)(arow + kn + kfa * 4);
            ra1 = *(const float4*)(arow + kn + (kfa + 4) * 4);
#pragma unroll
            for (int j = 0; j < 8; j++)
                rb[j] = *(const float4*)(Bbase + (size_t)(nb + j * 16) * K_DIM + kn + kfb * 4);
        }

#pragma unroll
        for (int kk = 0; kk < 4; kk++) {
            const int ks = kk * 8 + (lane & 3);
            uint32_t a[2][4];
#pragma unroll
            for (int mf = 0; mf < 2; mf++) {
                int r = mf * 16 + (lane >> 2);
                a[mf][0] = Asu[r * STRIDE + ks];
                a[mf][1] = Asu[(r + 8) * STRIDE + ks];
                a[mf][2] = Asu[r * STRIDE + ks + 4];
                a[mf][3] = Asu[(r + 8) * STRIDE + ks + 4];
            }
#pragma unroll
            for (int nf = 0; nf < 4; nf++) {
                uint32_t b[2];
                int c = warp * 32 + nf * 8 + (lane >> 2);
                b[0] = Bsu[c * STRIDE + ks];
                b[1] = Bsu[c * STRIDE + ks + 4];
                mma_tf32(acc[0][nf], a[0], b);
                mma_tf32(acc[1][nf], a[1], b);
            }
        }
        __syncthreads();
    }

    // epilogue: (acc + bias[e][n]) * w[l], scattered to out[l]
#pragma unroll
    for (int mf = 0; mf < 2; mf++) {
#pragma unroll
        for (int nf = 0; nf < 4; nf++) {
            int r   = mf * 16 + (lane >> 2);
            int col = n0 + warp * 32 + nf * 8 + (lane & 3) * 2;
            float2 bv = *(const float2*)(bias + (size_t)e * N_DIM + col);
            {
                int l = sSlot[r]; float wv = sW[r];
                float2 o = { (acc[mf][nf][0] + bv.x) * wv,
                             (acc[mf][nf][1] + bv.y) * wv };
                *(float2*)(out + (size_t)l * N_DIM + col) = o;
            }
            {
                int l = sSlot[r + 8]; float wv = sW[r + 8];
                float2 o = { (acc[mf][nf][2] + bv.x) * wv,
                             (acc[mf][nf][3] + bv.y) * wv };
                *(float2*)(out + (size_t)l * N_DIM + col) = o;
            }
        }
    }
}

extern "C" void kernel_launch(void* const* d_in, const int* in_sizes, int n_in,
                              void* d_out, int out_size) {
    (void)in_sizes; (void)n_in; (void)out_size;
    const float* A    = (const float*)d_in[0];   // [M, K] fp32
    const float* B    = (const float*)d_in[1];   // [E, N, K] fp32
    const float* bias = (const float*)d_in[2];   // [E, N] fp32
    const float* tw   = (const float*)d_in[3];   // [M, TOPK] fp32
    const int*   ids  = (const int*)d_in[4];     // [M, TOPK] int32
    float* out = (float*)d_out;                  // [M, TOPK, N] fp32

    route_kernel<<<1, 1024>>>(ids);
    cvtA_kernel<<<(M_TOK * K_DIM + 255) / 256, 256>>>(A);
    moe_gemm_kernel<<<dim3(N_DIM / BN, E_NUM), THREADS>>>(B, bias, tw, out);
}